// round 2
// baseline (speedup 1.0000x reference)
#include <cuda_runtime.h>
#include <cuda_bf16.h>
#include <cstddef>

#define RR   7
#define KS   15          // kernel side = 2R+1
#define NK   (KS*KS)     // 225
#define BATCH 8
#define HI   512
#define WI   512
#define HO   256         // HI/2 (stride 2)
#define WO   256
#define TX   256         // output tile width per block = FULL row
#define TY   4           // output tile height per block
#define SW   (TX + 2*RR) // 270
#define SH   (TY + 2*RR) // 18

__global__ __launch_bounds__(256, 4)
void adj_equality_kernel(const float* __restrict__ in, float* __restrict__ out)
{
    __shared__ float tile[SH][SW];

    const int by = blockIdx.x;          // 0..63  (HO/TY)
    const int b  = blockIdx.y;          // 0..7
    const int tid = threadIdx.x;        // 0..255

    const int y0 = by * TY;

    // ---- Load tile + halo (zero padding outside), downsampling stride-2 on the fly ----
    const float* __restrict__ inb = in + (size_t)b * HI * WI;
    for (int i = tid; i < SH * SW; i += 256) {
        const int r = i / SW;
        const int c = i - r * SW;
        const int gy = y0 + r - RR;     // downsampled coords
        const int gx = c - RR;
        float v = 0.0f;
        if (gy >= 0 && gy < HO && gx >= 0 && gx < WO)
            v = inb[(size_t)(gy * 2) * WI + (size_t)(gx * 2)];
        tile[r][c] = v;
    }
    __syncthreads();

    // ---- 64 threads per output row x 4 rows; each thread owns 4 contiguous cols ----
    const int tx = tid & 63;            // 0..63
    const int ty = tid >> 6;            // 0..3
    const int lx = tx * 4;              // 0..252 local x
    const int ly = ty;                  // local y

    const float c0 = tile[ly + RR][lx + RR + 0];
    const float c1 = tile[ly + RR][lx + RR + 1];
    const float c2 = tile[ly + RR][lx + RR + 2];
    const float c3 = tile[ly + RR][lx + RR + 3];

    const int oy = y0 + ly;
    float* __restrict__ outb = out + (size_t)b * NK * HO * WO
                                   + (size_t)oy * WO + lx;

    // dy rolled (keeps body in L0 I$), dx fully unrolled (static reg indexing)
    for (int dy = 0; dy < KS; ++dy) {
        // slide-window register cache: 18 consecutive floats of this smem row
        float nb[KS + 3];
        #pragma unroll
        for (int j = 0; j < KS + 3; ++j)
            nb[j] = tile[ly + dy][lx + j];

        float* __restrict__ orow = outb + (size_t)(dy * KS) * HO * WO;
        #pragma unroll
        for (int dx = 0; dx < KS; ++dx) {
            float4 v;
            v.x = (nb[dx + 0] == c0) ? 1.0f : 0.0f;
            v.y = (nb[dx + 1] == c1) ? 1.0f : 0.0f;
            v.z = (nb[dx + 2] == c2) ? 1.0f : 0.0f;
            v.w = (nb[dx + 3] == c3) ? 1.0f : 0.0f;
            // streaming store: output is never re-read, keep it out of L2's way
            __stcs(reinterpret_cast<float4*>(orow + (size_t)dx * HO * WO), v);
        }
    }
}

extern "C" void kernel_launch(void* const* d_in, const int* in_sizes, int n_in,
                              void* d_out, int out_size)
{
    const float* segments = (const float*)d_in[0];
    float* out = (float*)d_out;

    dim3 grid(HO / TY, BATCH);          // (64, 8) = 512 blocks
    dim3 block(256);
    adj_equality_kernel<<<grid, block>>>(segments, out);
}

// round 3
// speedup vs baseline: 1.2032x; 1.2032x over previous
#include <cuda_runtime.h>
#include <cuda_bf16.h>
#include <cstddef>

#define RR   7
#define KS   15            // 2R+1
#define NK   (KS*KS)       // 225
#define BATCH 8
#define HI   512
#define WI   512
#define HO   256
#define WO   256
#define TY   4             // output rows per block
#define SW   (WO + 2*RR)   // 270 (x window with halo)
#define SWP  280           // padded smem row stride
#define NBLK (BATCH * (HO/TY) * KS)   // 8*64*15 = 7680
#define DYN_SMEM 46080     // caps occupancy at 4 CTAs/SM (4*46080=184KB <= 228KB)

__global__ __launch_bounds__(256)
void adj_equality_kernel(const float* __restrict__ in, float* __restrict__ out)
{
    extern __shared__ float nb[];   // uses nb[0 .. 4*SWP)

    // item decode: (b, ytile, dy)
    const int item = blockIdx.x;
    const int dy   = item % KS;
    const int sp   = item / KS;          // 0..511
    const int yt   = sp & 63;            // 0..63
    const int b    = sp >> 6;            // 0..7
    const int y0   = yt * TY;

    const int tid = threadIdx.x;
    const float* __restrict__ inb = in + (size_t)b * HI * WI;

    // ---- Load 4 neighbor rows (rows y0+dy-7 .. y0+dy-4), x in [-7, 263),
    //      zero padding outside, stride-2 downsample on the fly ----
    #pragma unroll
    for (int k = 0; k < 5; ++k) {        // 5*256 >= 4*270
        const int i = tid + k * 256;
        if (i < TY * SW) {
            const int r = i / SW;
            const int c = i - r * SW;
            const int ny = y0 + r + dy - RR;    // neighbor row (downsampled coords)
            const int gx = c - RR;
            float v = 0.0f;
            if (ny >= 0 && ny < HO && gx >= 0 && gx < WO)
                v = inb[(size_t)(ny * 2) * WI + (size_t)(gx * 2)];
            nb[r * SWP + c] = v;
        }
    }

    // ---- Center values straight from global (L2-hot, tiny traffic) ----
    const int tx = tid & 63;             // 0..63
    const int ty = tid >> 6;             // 0..3
    const int lx = tx * 4;
    const int y  = y0 + ty;

    const float c0 = inb[(size_t)(y * 2) * WI + (size_t)((lx + 0) * 2)];
    const float c1 = inb[(size_t)(y * 2) * WI + (size_t)((lx + 1) * 2)];
    const float c2 = inb[(size_t)(y * 2) * WI + (size_t)((lx + 2) * 2)];
    const float c3 = inb[(size_t)(y * 2) * WI + (size_t)((lx + 3) * 2)];

    __syncthreads();

    // ---- Register window of the neighbor row: 18 consecutive floats ----
    float w[KS + 3];
    #pragma unroll
    for (int j = 0; j < KS + 3; ++j)
        w[j] = nb[ty * SWP + lx + j];

    float* __restrict__ outp = out + (size_t)b * NK * HO * WO
                                   + (size_t)(dy * KS) * HO * WO
                                   + (size_t)y * WO + lx;

    #pragma unroll
    for (int dx = 0; dx < KS; ++dx) {
        float4 v;
        v.x = (w[dx + 0] == c0) ? 1.0f : 0.0f;
        v.y = (w[dx + 1] == c1) ? 1.0f : 0.0f;
        v.z = (w[dx + 2] == c2) ? 1.0f : 0.0f;
        v.w = (w[dx + 3] == c3) ? 1.0f : 0.0f;
        *reinterpret_cast<float4*>(outp + (size_t)dx * HO * WO) = v;
    }
}

extern "C" void kernel_launch(void* const* d_in, const int* in_sizes, int n_in,
                              void* d_out, int out_size)
{
    const float* segments = (const float*)d_in[0];
    float* out = (float*)d_out;

    adj_equality_kernel<<<NBLK, 256, DYN_SMEM>>>(segments, out);
}